// round 3
// baseline (speedup 1.0000x reference)
#include <cuda_runtime.h>

#define IMG_H 256
#define IMG_W 256
#define KS    33
#define PADV  16
#define TX    32
#define TY    8
#define PW    (TX + KS - 1)   // 64
#define PH    (TY + KS - 1)   // 40
#define PLANE (IMG_H * IMG_W) // 65536

__global__ __launch_bounds__(TX * TY)
void reblur_dynconv_kernel(const float* __restrict__ img,
                           const float* __restrict__ ker,
                           float* __restrict__ out)
{
    __shared__ float s0[PH * PW];
    __shared__ float s1[PH * PW];
    __shared__ float s2[PH * PW];

    const int lx  = threadIdx.x;
    const int ly  = threadIdx.y;
    const int tid = ly * TX + lx;
    const int bx0 = blockIdx.x * TX;
    const int by0 = blockIdx.y * TY;

    // Cooperative load of the (replication-padded) input patch: 3 x 40x64 floats.
    #pragma unroll
    for (int i = tid; i < PH * PW; i += TX * TY) {
        const int py = i / PW;
        const int px = i - py * PW;
        int gy = by0 + py - PADV;
        int gx = bx0 + px - PADV;
        gy = gy < 0 ? 0 : (gy > IMG_H - 1 ? IMG_H - 1 : gy);
        gx = gx < 0 ? 0 : (gx > IMG_W - 1 ? IMG_W - 1 : gx);
        const int g = gy * IMG_W + gx;
        s0[i] = img[g];
        s1[i] = img[PLANE + g];
        s2[i] = img[2 * PLANE + g];
    }
    __syncthreads();

    const int x   = bx0 + lx;
    const int y   = by0 + ly;
    const int pix = y * IMG_W + x;
    const float* __restrict__ kp = ker + pix;

    float a0 = 0.0f, a1 = 0.0f, a2 = 0.0f;

    #pragma unroll 1
    for (int fh = 0; fh < KS; ++fh) {
        const float* __restrict__ r0 = &s0[(ly + fh) * PW + lx];
        const float* __restrict__ r1 = &s1[(ly + fh) * PW + lx];
        const float* __restrict__ r2 = &s2[(ly + fh) * PW + lx];
        const float* __restrict__ kr = kp + fh * KS * PLANE;
        #pragma unroll
        for (int fw = 0; fw < KS; ++fw) {
            float w = kr[fw * PLANE];          // coalesced HBM stream, batched MLP
            w = (w > 1e-4f) ? w : 0.0f;        // threshold, branch-free
            a0 = fmaf(w, r0[fw], a0);
            a1 = fmaf(w, r1[fw], a1);
            a2 = fmaf(w, r2[fw], a2);
        }
    }

    out[pix]             = a0;
    out[PLANE + pix]     = a1;
    out[2 * PLANE + pix] = a2;
}

extern "C" void kernel_launch(void* const* d_in, const int* in_sizes, int n_in,
                              void* d_out, int out_size)
{
    const float* img = (const float*)d_in[0];   // [1,3,256,256]
    const float* ker = (const float*)d_in[1];   // [1,1089,256,256]
    float* out = (float*)d_out;                 // [1,3,256,256]

    dim3 block(TX, TY);
    dim3 grid(IMG_W / TX, IMG_H / TY);          // 8 x 32 = 256 CTAs
    reblur_dynconv_kernel<<<grid, block>>>(img, ker, out);
}

// round 6
// speedup vs baseline: 1.5672x; 1.5672x over previous
#include <cuda_runtime.h>

#define IMG_H 256
#define IMG_W 256
#define KS    33
#define PADV  16
#define TX    32
#define TY    8
#define PW    (TX + KS - 1)    // 64
#define PLANE (IMG_H * IMG_W)  // 65536

#define GROUPS   4
#define FH_BASE  8             // groups: 8,8,8,9
#define PH_SUB   (TY - 1 + 9)  // 16 rows covers the worst (last) group

__global__ void zero_out_kernel(float* __restrict__ out)
{
    // 3*65536 floats = 49152 float4
    int i = blockIdx.x * blockDim.x + threadIdx.x;
    ((float4*)out)[i] = make_float4(0.f, 0.f, 0.f, 0.f);
}

__global__ __launch_bounds__(TX * TY)
void reblur_dynconv_part_kernel(const float* __restrict__ img,
                                const float* __restrict__ ker,
                                float* __restrict__ out)
{
    __shared__ float s0[PH_SUB * PW];
    __shared__ float s1[PH_SUB * PW];
    __shared__ float s2[PH_SUB * PW];

    const int lx  = threadIdx.x;
    const int ly  = threadIdx.y;
    const int tid = ly * TX + lx;
    const int bx0 = blockIdx.x * TX;
    const int by0 = blockIdx.y * TY;
    const int g   = blockIdx.z;
    const int f0  = g * FH_BASE;                  // 0,8,16,24
    const int fcnt = (g == GROUPS - 1) ? 9 : FH_BASE;

    // Cooperative load of the replication-padded sub-patch:
    // rows [by0 + f0 - PAD, by0 + f0 - PAD + PH_SUB), cols [bx0-PAD, bx0-PAD+PW)
    #pragma unroll
    for (int i = tid; i < PH_SUB * PW; i += TX * TY) {
        const int py = i >> 6;          // / PW (64)
        const int px = i & (PW - 1);
        int gy = by0 + f0 + py - PADV;
        int gx = bx0 + px - PADV;
        gy = gy < 0 ? 0 : (gy > IMG_H - 1 ? IMG_H - 1 : gy);
        gx = gx < 0 ? 0 : (gx > IMG_W - 1 ? IMG_W - 1 : gx);
        const int gi = gy * IMG_W + gx;
        s0[i] = img[gi];
        s1[i] = img[PLANE + gi];
        s2[i] = img[2 * PLANE + gi];
    }
    __syncthreads();

    const int x   = bx0 + lx;
    const int y   = by0 + ly;
    const int pix = y * IMG_W + x;
    const float* __restrict__ kp = ker + (size_t)f0 * KS * PLANE + pix;

    float a0 = 0.0f, a1 = 0.0f, a2 = 0.0f;

    #pragma unroll 1
    for (int fh = 0; fh < fcnt; ++fh) {
        const float* __restrict__ r0 = &s0[(ly + fh) * PW + lx];
        const float* __restrict__ r1 = &s1[(ly + fh) * PW + lx];
        const float* __restrict__ r2 = &s2[(ly + fh) * PW + lx];
        const float* __restrict__ kr = kp + (size_t)fh * KS * PLANE;
        #pragma unroll
        for (int fw = 0; fw < KS; ++fw) {
            float w = kr[(size_t)fw * PLANE];  // coalesced, one-use HBM stream
            w = (w > 1e-4f) ? w : 0.0f;        // threshold, branch-free
            a0 = fmaf(w, r0[fw], a0);
            a1 = fmaf(w, r1[fw], a1);
            a2 = fmaf(w, r2[fw], a2);
        }
    }

    atomicAdd(&out[pix],             a0);
    atomicAdd(&out[PLANE + pix],     a1);
    atomicAdd(&out[2 * PLANE + pix], a2);
}

extern "C" void kernel_launch(void* const* d_in, const int* in_sizes, int n_in,
                              void* d_out, int out_size)
{
    const float* img = (const float*)d_in[0];   // [1,3,256,256]
    const float* ker = (const float*)d_in[1];   // [1,1089,256,256]
    float* out = (float*)d_out;                 // [1,3,256,256]

    zero_out_kernel<<<(3 * PLANE / 4) / 256, 256>>>(out);

    dim3 block(TX, TY);
    dim3 grid(IMG_W / TX, IMG_H / TY, GROUPS);  // 8 x 32 x 4 = 1024 CTAs
    reblur_dynconv_part_kernel<<<grid, block>>>(img, ker, out);
}

// round 7
// speedup vs baseline: 1.6857x; 1.0756x over previous
#include <cuda_runtime.h>

#define IMG_H 256
#define IMG_W 256
#define KS    33
#define PADV  16
#define TX    32
#define TY    8
#define VEC   4                      // pixels per thread (float4 weight loads)
#define TILE_W (TX * VEC)            // 128
#define PW2   (TILE_W + KS - 1)      // 160 patch width
#define PLANE (IMG_H * IMG_W)        // 65536

#define GROUPS  11
#define FH_PER  3                    // 33 = 11 * 3, exact
#define PH_SUB  (TY - 1 + FH_PER)    // 10 patch rows per group

__global__ void zero_out_kernel(float* __restrict__ out)
{
    int i = blockIdx.x * blockDim.x + threadIdx.x;
    ((float4*)out)[i] = make_float4(0.f, 0.f, 0.f, 0.f);
}

__global__ __launch_bounds__(TX * TY)
void reblur_dynconv_v4_kernel(const float* __restrict__ img,
                              const float* __restrict__ ker,
                              float* __restrict__ out)
{
    __shared__ float s0[PH_SUB * PW2];
    __shared__ float s1[PH_SUB * PW2];
    __shared__ float s2[PH_SUB * PW2];

    const int lx  = threadIdx.x;
    const int ly  = threadIdx.y;
    const int tid = ly * TX + lx;
    const int bx0 = blockIdx.x * TILE_W;
    const int by0 = blockIdx.y * TY;
    const int f0  = blockIdx.z * FH_PER;          // first fh row of this group

    // Cooperative load of the replication-padded sub-patch:
    // rows [by0 + f0 - PAD, +PH_SUB), cols [bx0 - PAD, +PW2), 3 channels.
    for (int i = tid; i < PH_SUB * PW2; i += TX * TY) {
        const int py = i / PW2;
        const int px = i - py * PW2;
        int gy = by0 + f0 + py - PADV;
        int gx = bx0 + px - PADV;
        gy = gy < 0 ? 0 : (gy > IMG_H - 1 ? IMG_H - 1 : gy);
        gx = gx < 0 ? 0 : (gx > IMG_W - 1 ? IMG_W - 1 : gx);
        const int gi = gy * IMG_W + gx;
        s0[i] = img[gi];
        s1[i] = img[PLANE + gi];
        s2[i] = img[2 * PLANE + gi];
    }
    __syncthreads();

    const int x0  = bx0 + lx * VEC;               // first of 4 consecutive pixels
    const int y   = by0 + ly;
    const int pix = y * IMG_W + x0;
    // weight pointer for tap (f0, 0) at pixel x0 (16B-aligned: x0 % 4 == 0)
    const float* __restrict__ kp = ker + (size_t)f0 * KS * PLANE + pix;

    float a00 = 0.f, a01 = 0.f, a02 = 0.f, a03 = 0.f;   // channel 0, px 0..3
    float a10 = 0.f, a11 = 0.f, a12 = 0.f, a13 = 0.f;   // channel 1
    float a20 = 0.f, a21 = 0.f, a22 = 0.f, a23 = 0.f;   // channel 2

    #pragma unroll 1
    for (int fh = 0; fh < FH_PER; ++fh) {
        const float* __restrict__ r0 = &s0[(ly + fh) * PW2 + lx * VEC];
        const float* __restrict__ r1 = &s1[(ly + fh) * PW2 + lx * VEC];
        const float* __restrict__ r2 = &s2[(ly + fh) * PW2 + lx * VEC];
        const float* __restrict__ kr = kp + (size_t)fh * KS * PLANE;

        #pragma unroll
        for (int fw = 0; fw < KS; ++fw) {
            float4 w = *(const float4*)&kr[(size_t)fw * PLANE];  // 512B/warp in flight
            w.x = (w.x > 1e-4f) ? w.x : 0.0f;
            w.y = (w.y > 1e-4f) ? w.y : 0.0f;
            w.z = (w.z > 1e-4f) ? w.z : 0.0f;
            w.w = (w.w > 1e-4f) ? w.w : 0.0f;

            // sliding-window smem reads: r*[fw..fw+3] reused across fw (CSE)
            a00 = fmaf(w.x, r0[fw    ], a00);
            a01 = fmaf(w.y, r0[fw + 1], a01);
            a02 = fmaf(w.z, r0[fw + 2], a02);
            a03 = fmaf(w.w, r0[fw + 3], a03);

            a10 = fmaf(w.x, r1[fw    ], a10);
            a11 = fmaf(w.y, r1[fw + 1], a11);
            a12 = fmaf(w.z, r1[fw + 2], a12);
            a13 = fmaf(w.w, r1[fw + 3], a13);

            a20 = fmaf(w.x, r2[fw    ], a20);
            a21 = fmaf(w.y, r2[fw + 1], a21);
            a22 = fmaf(w.z, r2[fw + 2], a22);
            a23 = fmaf(w.w, r2[fw + 3], a23);
        }
    }

    atomicAdd(&out[pix    ], a00);
    atomicAdd(&out[pix + 1], a01);
    atomicAdd(&out[pix + 2], a02);
    atomicAdd(&out[pix + 3], a03);

    atomicAdd(&out[PLANE + pix    ], a10);
    atomicAdd(&out[PLANE + pix + 1], a11);
    atomicAdd(&out[PLANE + pix + 2], a12);
    atomicAdd(&out[PLANE + pix + 3], a13);

    atomicAdd(&out[2 * PLANE + pix    ], a20);
    atomicAdd(&out[2 * PLANE + pix + 1], a21);
    atomicAdd(&out[2 * PLANE + pix + 2], a22);
    atomicAdd(&out[2 * PLANE + pix + 3], a23);
}

extern "C" void kernel_launch(void* const* d_in, const int* in_sizes, int n_in,
                              void* d_out, int out_size)
{
    const float* img = (const float*)d_in[0];   // [1,3,256,256]
    const float* ker = (const float*)d_in[1];   // [1,1089,256,256]
    float* out = (float*)d_out;                 // [1,3,256,256]

    zero_out_kernel<<<(3 * PLANE / 4) / 256, 256>>>(out);

    dim3 block(TX, TY);
    dim3 grid(IMG_W / TILE_W, IMG_H / TY, GROUPS);  // 2 x 32 x 11 = 704 CTAs
    reblur_dynconv_v4_kernel<<<grid, block>>>(img, ker, out);
}